// round 8
// baseline (speedup 1.0000x reference)
#include <cuda_runtime.h>

#define NB 16
#define TT 1024
#define HH 1024
#define G3 3072
#define NPOS (NB*TT)
#define NTH_ELEMS (NB*TT*HH)
#define NCTA_W 296
#define WTHR 256
#define NGXT 6144   // gx tiles: 256 mb x (16 A-cols + 8 B-cols)

typedef unsigned long long u64;

// scratch
__device__ float    g_gx[(size_t)NPOS * G3];   // 192 MB, SLOT-ordered
__device__ float    g_rh[(size_t)NPOS * HH];
__device__ float    g_z [(size_t)NPOS * HH];
__device__ unsigned g_rbits[TT];
__device__ unsigned g_poslist[NPOS];
__device__ unsigned g_waveoff[TT + 1];
__device__ unsigned g_nwaves;
__device__ unsigned g_bar;
__device__ unsigned g_gxnext;
__device__ unsigned g_gxf[NGXT];               // indexed mb*24 + nt_global

// ---- packed fp32x2 helpers ----
__device__ __forceinline__ void fma2(u64& d, u64 a, u64 b) {
    asm("fma.rn.f32x2 %0, %1, %2, %0;" : "+l"(d) : "l"(a), "l"(b));
}
__device__ __forceinline__ u64 dup2(float x) {
    u64 r; asm("mov.b64 %0, {%1, %1};" : "=l"(r) : "f"(x)); return r;
}
__device__ __forceinline__ float2 unpk(u64 v) {
    float2 r; asm("mov.b64 {%0, %1}, %2;" : "=f"(r.x), "=f"(r.y) : "l"(v)); return r;
}
__device__ __forceinline__ float sigm(float x) {
    return 1.f / (1.f + __expf(-x));
}

// ---------------------------------------------------------------------------
// setup: reset sniff, bitmasks, wave decomposition, flag/counters reset
// ---------------------------------------------------------------------------
__global__ void setup_kernel(const void* __restrict__ reset_raw,
                             const float* __restrict__ initial_h,
                             float* __restrict__ out) {
    __shared__ unsigned hist[TT];
    __shared__ unsigned curs[TT];
    __shared__ unsigned rbs[TT];
    __shared__ unsigned short depth[NB][TT];
    __shared__ int s_i32, s_f32;
    const int tid = threadIdx.x;
    if (tid == 0) { s_i32 = 1; s_f32 = 1; }
    __syncthreads();
    {
        const unsigned* rw = (const unsigned*)reset_raw;
        int bad_i = 0, bad_f = 0;
        for (int q = tid; q < 4096; q += 256) {
            unsigned v = rw[q];
            if (v > 1u) bad_i = 1;
            if (v != 0u && v != 0x3F800000u) bad_f = 1;
        }
        if (bad_i) s_i32 = 0;
        if (bad_f) s_f32 = 0;
    }
    __syncthreads();
    const int rmode = s_i32 ? 0 : (s_f32 ? 1 : 2);
    const int*           r32 = (const int*)reset_raw;
    const float*         rf  = (const float*)reset_raw;
    const unsigned char* r8  = (const unsigned char*)reset_raw;

    for (int t = tid; t < TT; t += 256) {
        unsigned m = 0;
#pragma unroll
        for (int n = 0; n < NB; n++) {
            bool rv = (rmode == 0) ? (r32[n * TT + t] != 0)
                    : (rmode == 1) ? (rf[n * TT + t] != 0.f)
                                   : (r8[n * TT + t] != 0);
            m |= (unsigned)rv << n;
        }
        rbs[t] = m;
        g_rbits[t] = m;
        hist[t] = 0;
    }
    for (int i = tid; i < NGXT; i += 256) g_gxf[i] = 0u;
    __syncthreads();
    if (tid < NB) {
        unsigned short d = 0;
        for (int t = 0; t < TT; t++) {
            if (t == 0 || ((rbs[t] >> tid) & 1u)) d = 0; else d++;
            depth[tid][t] = d;
            atomicAdd(&hist[d], 1u);
        }
    }
    __syncthreads();
    if (tid == 0) {
        unsigned acc = 0, maxd = 0;
        for (int w0 = 0; w0 < TT; w0++) {
            unsigned c = hist[w0];
            if (c) maxd = (unsigned)w0;
            curs[w0] = acc;
            g_waveoff[w0] = acc;
            acc += c;
        }
        g_waveoff[TT] = acc;
        g_nwaves = maxd + 1;
        g_bar = 0u;
        g_gxnext = 0u;
    }
    __syncthreads();
    for (int p = tid; p < NPOS; p += 256) {
        int n = p >> 10, t = p & 1023;
        unsigned d = depth[n][t];
        unsigned slot = atomicAdd(&curs[d], 1u);
        g_poslist[slot] = (unsigned)p;
    }
    for (int q = tid; q < HH; q += 256)
        out[2 * (size_t)NTH_ELEMS + q] = initial_h[q];
}

// ---------------------------------------------------------------------------
struct WaveCtx {
    const float* carry;
    const float* initial_h;
    const float* w_h;
    const float* bias;
    const float* x;
    const float* w_i;
    float* out;
    float* AsRaw;                 // union: As8[2][16][132] / As[2][32][64]
    float (*Bs)[32][128];
    const unsigned* rbs;
    const float** rowp;
    unsigned* posv;
    volatile unsigned* bc;        // [0]=steal idx, [1]=wait status
};

// ---------------------------------------------------------------------------
// gx steal tile: 64 gathered x-rows (slots mb*64..) x 128 w_i cols, K=1024
// ---------------------------------------------------------------------------
__device__ void gx_tile(const WaveCtx& C, unsigned v) {
    const int tid = threadIdx.x;
    const int tx = tid & 15;
    const int ty = tid >> 4;
    int mb, nt;
    if (v < 4096u) { mb = (int)(v >> 4); nt = (int)(v & 15u); }
    else { unsigned w = v - 4096u; mb = (int)(w >> 3); nt = 16 + (int)(w & 7u); }
    const int s0 = mb * 64;
    float (*As)[32][64] = (float(*)[32][64])C.AsRaw;

    __syncthreads();
    if (tid < 64)
        C.rowp[tid] = C.x + (size_t)g_poslist[s0 + tid] * HH;
    __syncthreads();

    const float* wb = C.w_i + nt * 128;

    u64 acc[4][4];
#pragma unroll
    for (int r = 0; r < 4; r++)
#pragma unroll
        for (int j = 0; j < 4; j++) acc[r][j] = 0ull;

    float4 aL[2], bL[4];
    auto loadA = [&](int k0) {
#pragma unroll
        for (int c = 0; c < 2; c++) {
            int q = tid + 256 * c;
            int i = q & 63, kc = q >> 6;
            aL[c] = __ldcg((const float4*)(C.rowp[i] + k0 + kc * 4));
        }
    };
    auto storeA = [&](int buf) {
#pragma unroll
        for (int c = 0; c < 2; c++) {
            int q = tid + 256 * c;
            int i = q & 63, kc = q >> 6;
            As[buf][kc * 4 + 0][i] = aL[c].x;
            As[buf][kc * 4 + 1][i] = aL[c].y;
            As[buf][kc * 4 + 2][i] = aL[c].z;
            As[buf][kc * 4 + 3][i] = aL[c].w;
        }
    };
    auto loadB = [&](int k0) {
#pragma unroll
        for (int c = 0; c < 4; c++) {
            int q = tid + 256 * c;
            int row = q >> 5, c4 = q & 31;
            bL[c] = __ldcg((const float4*)(wb + (size_t)(k0 + row) * G3 + c4 * 4));
        }
    };
    auto storeB = [&](int buf) {
#pragma unroll
        for (int c = 0; c < 4; c++) {
            int q = tid + 256 * c;
            int row = q >> 5, c4 = q & 31;
            *(float4*)&C.Bs[buf][row][c4 * 4] = bL[c];
        }
    };

    loadA(0); loadB(0);
    storeA(0); storeB(0);
    for (int it = 0; it < 32; it++) {
        __syncthreads();
        const int db = it & 1;
        if (it < 31) { loadA((it + 1) * 32); loadB((it + 1) * 32); }
#pragma unroll
        for (int kk = 0; kk < 32; kk++) {
            float4 a4 = *(const float4*)&As[db][kk][ty * 4];
            ulonglong2 b01 = *(const ulonglong2*)&C.Bs[db][kk][tx * 8];
            ulonglong2 b23 = *(const ulonglong2*)&C.Bs[db][kk][tx * 8 + 4];
            float av[4] = {a4.x, a4.y, a4.z, a4.w};
#pragma unroll
            for (int r = 0; r < 4; r++) {
                u64 ar = dup2(av[r]);
                fma2(acc[r][0], ar, b01.x);
                fma2(acc[r][1], ar, b01.y);
                fma2(acc[r][2], ar, b23.x);
                fma2(acc[r][3], ar, b23.y);
            }
        }
        if (it < 31) { const int nb = db ^ 1; storeA(nb); storeB(nb); }
    }

#pragma unroll
    for (int r = 0; r < 4; r++) {
        int row = ty * 4 + r;
        float* dst = g_gx + (size_t)(s0 + row) * G3 + nt * 128 + tx * 8;
        float2 c0 = unpk(acc[r][0]);
        float2 c1 = unpk(acc[r][1]);
        float2 c2 = unpk(acc[r][2]);
        float2 c3 = unpk(acc[r][3]);
        *(float4*)dst       = make_float4(c0.x, c0.y, c1.x, c1.y);
        *(float4*)(dst + 4) = make_float4(c2.x, c2.y, c3.x, c3.y);
    }
    __threadfence();
    __syncthreads();
    // FIX: publish at the SAME index the waiter polls: mb*24 + nt_global
    if (tid == 0) atomicExch(&g_gxf[mb * 24 + nt], 1u);
}

// ---- steal one gx tile; false when pool exhausted ----
__device__ bool steal_one(const WaveCtx& C) {
    const int tid = threadIdx.x;
    __syncthreads();
    if (tid == 0) {
        unsigned v = NGXT;
        if (*(volatile unsigned*)&g_gxnext < NGXT)
            v = atomicAdd(&g_gxnext, 1u);
        C.bc[0] = v;
    }
    __syncthreads();
    unsigned v = C.bc[0];
    if (v >= NGXT) return false;
    gx_tile(C, v);
    return true;
}

// ---- wait until gx flags [mb0..mb1] x nt are set, stealing meanwhile ----
__device__ void wait_gx(const WaveCtx& C, int mb0, int mb1, int nt) {
    for (;;) {
        __syncthreads();
        if (threadIdx.x == 0) {
            unsigned ok = 1;
            for (int mb = mb0; mb <= mb1; mb++) {
                unsigned f;
                asm volatile("ld.acquire.gpu.global.u32 %0, [%1];"
                             : "=r"(f) : "l"(&g_gxf[mb * 24 + nt]) : "memory");
                ok &= f;
            }
            C.bc[1] = ok;
        }
        __syncthreads();
        if (C.bc[1]) return;
        if (!steal_one(C)) __nanosleep(200);
    }
}

// ---- grid barrier that steals gx tiles while waiting ----
__device__ void grid_barrier_steal(const WaveCtx& C, unsigned target) {
    __syncthreads();
    if (threadIdx.x == 0)
        asm volatile("red.release.gpu.global.add.u32 [%0], 1;"
                     :: "l"(&g_bar) : "memory");
    for (;;) {
        __syncthreads();
        if (threadIdx.x == 0) {
            unsigned v;
            asm volatile("ld.acquire.gpu.global.u32 %0, [%1];"
                         : "=r"(v) : "l"(&g_bar) : "memory");
            C.bc[1] = (v >= target) ? 1u : 0u;
        }
        __syncthreads();
        if (C.bc[1]) break;
        if (!steal_one(C)) __nanosleep(200);
    }
}

// ---------------------------------------------------------------------------
__device__ __forceinline__ void set_rows(const WaveCtx& C, int phase,
                                         int mtile, int POSB,
                                         unsigned base, unsigned cnt) {
    const int tid = threadIdx.x;
    __syncthreads();
    if (tid < POSB) {
        int idx = mtile * POSB + tid;
        unsigned pos = 0xFFFFFFFFu;
        const float* rp = C.initial_h;
        if ((unsigned)idx < cnt) {
            pos = g_poslist[base + idx];
            int n = pos >> 10, t = (int)(pos & 1023);
            if (phase)
                rp = g_rh + (size_t)pos * HH;
            else if ((C.rbs[t] >> n) & 1u)
                rp = C.initial_h;
            else if (t == 0)
                rp = C.carry + (size_t)n * TT * HH;
            else
                rp = C.out + (size_t)(pos - 1) * HH;
        }
        C.posv[tid] = pos;
        C.rowp[tid] = rp;
    }
    __syncthreads();
}

__device__ __forceinline__ void epilogue_row(const WaveCtx& C, int phase,
                                             int colbase, int tx,
                                             unsigned pos, unsigned slot,
                                             const float* rowptr,
                                             const u64* accq) {
    float res[8];
#pragma unroll
    for (int q = 0; q < 4; q++) {
        float2 f = unpk(accq[q]);
        res[2 * q] = f.x; res[2 * q + 1] = f.y;
    }
    const int col0 = colbase + tx * 8;
    const float* gxp = g_gx + (size_t)slot * G3 + col0;
    float4 gx0 = __ldcg((const float4*)gxp);
    float4 gx1 = __ldcg((const float4*)(gxp + 4));
    float gg[8] = {gx0.x, gx0.y, gx0.z, gx0.w, gx1.x, gx1.y, gx1.z, gx1.w};
    float4 bb0 = *(const float4*)(C.bias + col0);
    float4 bb1 = *(const float4*)(C.bias + col0 + 4);
    float bb[8] = {bb0.x, bb0.y, bb0.z, bb0.w, bb1.x, bb1.y, bb1.z, bb1.w};

    if (phase == 0 && col0 < HH) {
        float o[8];
#pragma unroll
        for (int s = 0; s < 8; s++) o[s] = sigm(gg[s] + res[s] + bb[s]);
        float* zp = g_z + (size_t)pos * HH + col0;
        *(float4*)zp       = make_float4(o[0], o[1], o[2], o[3]);
        *(float4*)(zp + 4) = make_float4(o[4], o[5], o[6], o[7]);
    } else if (phase == 0) {
        const int j0 = col0 - HH;
        float4 h0 = __ldcg((const float4*)(rowptr + j0));
        float4 h1 = __ldcg((const float4*)(rowptr + j0 + 4));
        float hh[8] = {h0.x, h0.y, h0.z, h0.w, h1.x, h1.y, h1.z, h1.w};
        float o[8];
#pragma unroll
        for (int s = 0; s < 8; s++)
            o[s] = sigm(gg[s] + res[s] + bb[s]) * hh[s];
        float* rp = g_rh + (size_t)pos * HH + j0;
        *(float4*)rp       = make_float4(o[0], o[1], o[2], o[3]);
        *(float4*)(rp + 4) = make_float4(o[4], o[5], o[6], o[7]);
    } else {
        const int j0 = col0 - 2 * HH;
        int n = pos >> 10, t = (int)(pos & 1023);
        const float* hp = ((C.rbs[t] >> n) & 1u) ? C.initial_h
                        : (t == 0 ? C.carry + (size_t)n * TT * HH
                                  : C.out + (size_t)(pos - 1) * HH);
        float4 h0 = __ldcg((const float4*)(hp + j0));
        float4 h1 = __ldcg((const float4*)(hp + j0 + 4));
        float hh[8] = {h0.x, h0.y, h0.z, h0.w, h1.x, h1.y, h1.z, h1.w};
        const float* zp = g_z + (size_t)pos * HH + j0;
        float4 z0 = __ldcg((const float4*)zp);
        float4 z1 = __ldcg((const float4*)(zp + 4));
        float zz[8] = {z0.x, z0.y, z0.z, z0.w, z1.x, z1.y, z1.z, z1.w};
        float o[8];
#pragma unroll
        for (int s = 0; s < 8; s++) {
            float a = tanhf(gg[s] + res[s] + bb[s]);
            o[s] = (1.f - zz[s]) * hh[s] + zz[s] * a;
        }
        float* op = C.out + (size_t)pos * HH + j0;
        float4 lo = make_float4(o[0], o[1], o[2], o[3]);
        float4 hi = make_float4(o[4], o[5], o[6], o[7]);
        *(float4*)op                    = lo;
        *(float4*)(op + 4)              = hi;
        *(float4*)(op + NTH_ELEMS)      = lo;
        *(float4*)(op + NTH_ELEMS + 4)  = hi;
    }
}

// ---------------------------------------------------------------------------
#define AS8_STRIDE 132
__device__ void gemm_tile8(const WaveCtx& C, int phase, int mtile, int ntile,
                           unsigned base, unsigned cnt) {
    const int tid = threadIdx.x;
    const int tx = tid & 15;
    const int ty = tid >> 4;
    float* As8 = C.AsRaw;
    float (*Bs8)[16][128] = (float(*)[16][128])C.Bs;

    {
        unsigned t0 = base + (unsigned)mtile * 128u;
        int mb0 = (int)(t0 >> 6);
        int mb1 = (int)((t0 + 127u) >> 6); if (mb1 > 255) mb1 = 255;
        wait_gx(C, mb0, mb1, phase ? 16 + ntile : ntile);
    }
    set_rows(C, phase, mtile, 128, base, cnt);

    const int colbase = (phase ? 2 * HH : 0) + ntile * 128;
    const float* wb = C.w_h + colbase;

    u64 acc[8][4];
#pragma unroll
    for (int r = 0; r < 8; r++)
#pragma unroll
        for (int j = 0; j < 4; j++) acc[r][j] = 0ull;

    float4 aL[2], bL[2];
    auto loadA = [&](int k0) {
#pragma unroll
        for (int p = 0; p < 2; p++) {
            int q = tid + 256 * p;
            int r = q >> 2, c4 = q & 3;
            aL[p] = __ldcg((const float4*)(C.rowp[r] + k0 + c4 * 4));
        }
    };
    auto storeA = [&](int buf) {
        float* bp = As8 + buf * 16 * AS8_STRIDE;
#pragma unroll
        for (int p = 0; p < 2; p++) {
            int q = tid + 256 * p;
            int r = q >> 2, c4 = q & 3;
            bp[(c4 * 4 + 0) * AS8_STRIDE + r] = aL[p].x;
            bp[(c4 * 4 + 1) * AS8_STRIDE + r] = aL[p].y;
            bp[(c4 * 4 + 2) * AS8_STRIDE + r] = aL[p].z;
            bp[(c4 * 4 + 3) * AS8_STRIDE + r] = aL[p].w;
        }
    };
    auto loadB = [&](int k0) {
#pragma unroll
        for (int p = 0; p < 2; p++) {
            int q = tid + 256 * p;
            int krow = q >> 5, col4 = q & 31;
            bL[p] = __ldcg((const float4*)(wb + (size_t)(k0 + krow) * G3 + col4 * 4));
        }
    };
    auto storeB = [&](int buf) {
#pragma unroll
        for (int p = 0; p < 2; p++) {
            int q = tid + 256 * p;
            int krow = q >> 5, col4 = q & 31;
            *(float4*)&Bs8[buf][krow][col4 * 4] = bL[p];
        }
    };

    loadA(0); loadB(0);
    storeA(0); storeB(0);
    for (int it = 0; it < 64; it++) {
        __syncthreads();
        const int db = it & 1;
        if (it < 63) { loadA((it + 1) * 16); loadB((it + 1) * 16); }
        const float* ab = As8 + db * 16 * AS8_STRIDE;
#pragma unroll
        for (int kk = 0; kk < 16; kk++) {
            float4 a0 = *(const float4*)(ab + kk * AS8_STRIDE + ty * 8);
            float4 a1 = *(const float4*)(ab + kk * AS8_STRIDE + ty * 8 + 4);
            ulonglong2 b01 = *(const ulonglong2*)&Bs8[db][kk][tx * 8];
            ulonglong2 b23 = *(const ulonglong2*)&Bs8[db][kk][tx * 8 + 4];
            float av[8] = {a0.x, a0.y, a0.z, a0.w, a1.x, a1.y, a1.z, a1.w};
#pragma unroll
            for (int r = 0; r < 8; r++) {
                u64 ar = dup2(av[r]);
                fma2(acc[r][0], ar, b01.x);
                fma2(acc[r][1], ar, b01.y);
                fma2(acc[r][2], ar, b23.x);
                fma2(acc[r][3], ar, b23.y);
            }
        }
        if (it < 63) { const int nb = db ^ 1; storeA(nb); storeB(nb); }
    }

#pragma unroll
    for (int r = 0; r < 8; r++) {
        const int i = ty * 8 + r;
        unsigned pos = C.posv[i];
        if (pos == 0xFFFFFFFFu) continue;
        unsigned slot = base + (unsigned)mtile * 128u + (unsigned)i;
        epilogue_row(C, phase, colbase, tx, pos, slot, C.rowp[i], acc[r]);
    }
}

// ---------------------------------------------------------------------------
template<int R>
__device__ void gemm_tile(const WaveCtx& C, int phase, int mtile, int ntile,
                          unsigned base, unsigned cnt) {
    constexpr int POSB = R * 16;
    const int tid = threadIdx.x;
    const int tx = tid & 15;
    const int ty = tid >> 4;
    float (*As)[32][64] = (float(*)[32][64])C.AsRaw;

    {
        unsigned t0 = base + (unsigned)(mtile * POSB);
        int mb0 = (int)(t0 >> 6);
        int mb1 = (int)((t0 + POSB - 1u) >> 6); if (mb1 > 255) mb1 = 255;
        wait_gx(C, mb0, mb1, phase ? 16 + ntile : ntile);
    }
    set_rows(C, phase, mtile, POSB, base, cnt);

    const int colbase = (phase ? 2 * HH : 0) + ntile * 128;
    const float* wb = C.w_h + colbase;

    u64 acc[R][4];
#pragma unroll
    for (int r = 0; r < R; r++)
#pragma unroll
        for (int j = 0; j < 4; j++) acc[r][j] = 0ull;

    float4 aL[2], bL[4];
    auto loadA = [&](int k0) {
        if (R == 4) {
#pragma unroll
            for (int c = 0; c < 2; c++) {
                int q = tid + 256 * c;
                int i = q & 63, kc = q >> 6;
                aL[c] = __ldcg((const float4*)(C.rowp[i] + k0 + kc * 4));
            }
        } else {
            if (tid < 128) {
                int i = tid & 15, kc = tid >> 4;
                aL[0] = __ldcg((const float4*)(C.rowp[i] + k0 + kc * 4));
            }
        }
    };
    auto storeA = [&](int buf) {
        if (R == 4) {
#pragma unroll
            for (int c = 0; c < 2; c++) {
                int q = tid + 256 * c;
                int i = q & 63, kc = q >> 6;
                As[buf][kc * 4 + 0][i] = aL[c].x;
                As[buf][kc * 4 + 1][i] = aL[c].y;
                As[buf][kc * 4 + 2][i] = aL[c].z;
                As[buf][kc * 4 + 3][i] = aL[c].w;
            }
        } else {
            if (tid < 128) {
                int i = tid & 15, kc = tid >> 4;
                As[buf][kc * 4 + 0][i] = aL[0].x;
                As[buf][kc * 4 + 1][i] = aL[0].y;
                As[buf][kc * 4 + 2][i] = aL[0].z;
                As[buf][kc * 4 + 3][i] = aL[0].w;
            }
        }
    };
    auto loadB = [&](int k0) {
#pragma unroll
        for (int c = 0; c < 4; c++) {
            int q = tid + 256 * c;
            int row = q >> 5, c4 = q & 31;
            bL[c] = __ldcg((const float4*)(wb + (size_t)(k0 + row) * G3 + c4 * 4));
        }
    };
    auto storeB = [&](int buf) {
#pragma unroll
        for (int c = 0; c < 4; c++) {
            int q = tid + 256 * c;
            int row = q >> 5, c4 = q & 31;
            *(float4*)&C.Bs[buf][row][c4 * 4] = bL[c];
        }
    };

    loadA(0); loadB(0);
    storeA(0); storeB(0);
    for (int it = 0; it < 32; it++) {
        __syncthreads();
        const int db = it & 1;
        if (it < 31) { loadA((it + 1) * 32); loadB((it + 1) * 32); }
#pragma unroll
        for (int kk = 0; kk < 32; kk++) {
            float av[R];
            if (R == 4) {
                float4 a4 = *(const float4*)&As[db][kk][ty * 4];
                av[0] = a4.x; av[1] = a4.y; av[2] = a4.z; av[3] = a4.w;
            } else {
                av[0] = As[db][kk][ty];
            }
            ulonglong2 b01 = *(const ulonglong2*)&C.Bs[db][kk][tx * 8];
            ulonglong2 b23 = *(const ulonglong2*)&C.Bs[db][kk][tx * 8 + 4];
#pragma unroll
            for (int r = 0; r < R; r++) {
                u64 ar = dup2(av[r]);
                fma2(acc[r][0], ar, b01.x);
                fma2(acc[r][1], ar, b01.y);
                fma2(acc[r][2], ar, b23.x);
                fma2(acc[r][3], ar, b23.y);
            }
        }
        if (it < 31) { const int nb = db ^ 1; storeA(nb); storeB(nb); }
    }

#pragma unroll
    for (int r = 0; r < R; r++) {
        const int i = ty * R + r;
        unsigned pos = C.posv[i];
        if (pos == 0xFFFFFFFFu) continue;
        unsigned slot = base + (unsigned)(mtile * POSB) + (unsigned)i;
        epilogue_row(C, phase, colbase, tx, pos, slot, C.rowp[i], acc[r]);
    }
}

// ---------------------------------------------------------------------------
__global__ void __launch_bounds__(WTHR, 2) wave_kernel(
        const float* __restrict__ carry,
        const float* __restrict__ initial_h,
        const float* __restrict__ w_h,
        const float* __restrict__ bias,
        const float* __restrict__ x,
        const float* __restrict__ w_i,
        float* __restrict__ out) {
    extern __shared__ char smw[];
    WaveCtx C;
    C.AsRaw = (float*)smw;                              // 16896 B
    C.Bs    = (float(*)[32][128])(smw + 16896);         // 32768 B
    unsigned* rbs = (unsigned*)(smw + 49664);           //  4096 B
    C.rowp  = (const float**)(smw + 53760);             //  1024 B
    C.posv  = (unsigned*)(smw + 54784);                 //   512 B
    C.bc    = (volatile unsigned*)(smw + 55296);        //    64 B
    C.rbs = rbs;
    C.carry = carry; C.initial_h = initial_h;
    C.w_h = w_h; C.bias = bias; C.out = out;
    C.x = x; C.w_i = w_i;

    const int tid = threadIdx.x;
    for (int t = tid; t < TT; t += WTHR) rbs[t] = g_rbits[t];
    __syncthreads();

    const unsigned nw = g_nwaves;
    unsigned bar_t = 0;

    for (unsigned wv = 0; wv < nw; wv++) {
        const unsigned base = g_waveoff[wv];
        const unsigned cnt  = g_waveoff[wv + 1] - base;
        const int kind = (cnt >= 1536) ? 2 : (cnt >= 256 ? 1 : 0);
        const int mt = (kind == 2) ? (int)((cnt + 127) >> 7)
                     : (kind == 1) ? (int)((cnt + 63) >> 6)
                                   : (int)((cnt + 15) >> 4);

        for (int tile = blockIdx.x; tile < mt * 16; tile += NCTA_W) {
            if (kind == 2)      gemm_tile8(C, 0, tile >> 4, tile & 15, base, cnt);
            else if (kind == 1) gemm_tile<4>(C, 0, tile >> 4, tile & 15, base, cnt);
            else                gemm_tile<1>(C, 0, tile >> 4, tile & 15, base, cnt);
        }
        bar_t += NCTA_W;
        grid_barrier_steal(C, bar_t);

        for (int tile = blockIdx.x; tile < mt * 8; tile += NCTA_W) {
            if (kind == 2)      gemm_tile8(C, 1, tile >> 3, tile & 7, base, cnt);
            else if (kind == 1) gemm_tile<4>(C, 1, tile >> 3, tile & 7, base, cnt);
            else                gemm_tile<1>(C, 1, tile >> 3, tile & 7, base, cnt);
        }
        bar_t += NCTA_W;
        grid_barrier_steal(C, bar_t);
    }
}

// ---------------------------------------------------------------------------
extern "C" void kernel_launch(void* const* d_in, const int* in_sizes, int n_in,
                              void* d_out, int out_size) {
    const float* x         = (const float*)d_in[0];
    const void*  reset     = d_in[1];
    const float* carry     = (const float*)d_in[2];
    const float* initial_h = (const float*)d_in[3];
    const float* w_i       = (const float*)d_in[4];
    const float* w_h       = (const float*)d_in[5];
    const float* b         = (const float*)d_in[6];
    float*       out       = (float*)d_out;
    (void)in_sizes; (void)n_in; (void)out_size;

    setup_kernel<<<1, 256>>>(reset, initial_h, out);

    size_t smem = 55360;
    cudaFuncSetAttribute((const void*)wave_kernel,
                         cudaFuncAttributeMaxDynamicSharedMemorySize, (int)smem);
    wave_kernel<<<NCTA_W, WTHR, smem>>>(carry, initial_h, w_h, b, x, w_i, out);
}

// round 9
// speedup vs baseline: 1.4995x; 1.4995x over previous
#include <cuda_runtime.h>

#define NB 16
#define TT 1024
#define HH 1024
#define G3 3072
#define NPOS (NB*TT)
#define NTH_ELEMS (NB*TT*HH)
#define NCTA_W 296
#define WTHR 256

typedef unsigned long long u64;

// scratch
__device__ float    g_gx[(size_t)NPOS * G3];   // 192 MB, position-ordered
__device__ float    g_rh[(size_t)NPOS * HH];
__device__ float    g_z [(size_t)NPOS * HH];
__device__ unsigned g_rbits[TT];
__device__ unsigned g_poslist[NPOS];
__device__ unsigned g_waveoff[TT + 1];
__device__ unsigned g_nwaves;
__device__ unsigned g_bar;

// ---- packed fp32x2 helpers ----
__device__ __forceinline__ void fma2(u64& d, u64 a, u64 b) {
    asm("fma.rn.f32x2 %0, %1, %2, %0;" : "+l"(d) : "l"(a), "l"(b));
}
__device__ __forceinline__ u64 dup2(float x) {
    u64 r; asm("mov.b64 %0, {%1, %1};" : "=l"(r) : "f"(x)); return r;
}
__device__ __forceinline__ float2 unpk(u64 v) {
    float2 r; asm("mov.b64 {%0, %1}, %2;" : "=f"(r.x), "=f"(r.y) : "l"(v)); return r;
}
__device__ __forceinline__ float sigm(float x) {
    return 1.f / (1.f + __expf(-x));
}

// ---------------------------------------------------------------------------
// setup: reset sniff, bitmasks, wave decomposition
// ---------------------------------------------------------------------------
__global__ void setup_kernel(const void* __restrict__ reset_raw,
                             const float* __restrict__ initial_h,
                             float* __restrict__ out) {
    __shared__ unsigned hist[TT];
    __shared__ unsigned curs[TT];
    __shared__ unsigned rbs[TT];
    __shared__ unsigned short depth[NB][TT];
    __shared__ int s_i32, s_f32;
    const int tid = threadIdx.x;
    if (tid == 0) { s_i32 = 1; s_f32 = 1; }
    __syncthreads();
    {
        const unsigned* rw = (const unsigned*)reset_raw;
        int bad_i = 0, bad_f = 0;
        for (int q = tid; q < 4096; q += 256) {
            unsigned v = rw[q];
            if (v > 1u) bad_i = 1;
            if (v != 0u && v != 0x3F800000u) bad_f = 1;
        }
        if (bad_i) s_i32 = 0;
        if (bad_f) s_f32 = 0;
    }
    __syncthreads();
    const int rmode = s_i32 ? 0 : (s_f32 ? 1 : 2);
    const int*           r32 = (const int*)reset_raw;
    const float*         rf  = (const float*)reset_raw;
    const unsigned char* r8  = (const unsigned char*)reset_raw;

    for (int t = tid; t < TT; t += 256) {
        unsigned m = 0;
#pragma unroll
        for (int n = 0; n < NB; n++) {
            bool rv = (rmode == 0) ? (r32[n * TT + t] != 0)
                    : (rmode == 1) ? (rf[n * TT + t] != 0.f)
                                   : (r8[n * TT + t] != 0);
            m |= (unsigned)rv << n;
        }
        rbs[t] = m;
        g_rbits[t] = m;
        hist[t] = 0;
    }
    __syncthreads();
    if (tid < NB) {
        unsigned short d = 0;
        for (int t = 0; t < TT; t++) {
            if (t == 0 || ((rbs[t] >> tid) & 1u)) d = 0; else d++;
            depth[tid][t] = d;
            atomicAdd(&hist[d], 1u);
        }
    }
    __syncthreads();
    if (tid == 0) {
        unsigned acc = 0, maxd = 0;
        for (int w0 = 0; w0 < TT; w0++) {
            unsigned c = hist[w0];
            if (c) maxd = (unsigned)w0;
            curs[w0] = acc;
            g_waveoff[w0] = acc;
            acc += c;
        }
        g_waveoff[TT] = acc;
        g_nwaves = maxd + 1;
        g_bar = 0u;
    }
    __syncthreads();
    for (int p = tid; p < NPOS; p += 256) {
        int n = p >> 10, t = p & 1023;
        unsigned d = depth[n][t];
        unsigned slot = atomicAdd(&curs[d], 1u);
        g_poslist[slot] = (unsigned)p;
    }
    for (int q = tid; q < HH; q += 256)
        out[2 * (size_t)NTH_ELEMS + q] = initial_h[q];
}

// ---------------------------------------------------------------------------
// gx = x @ w_i  (fp32 packed FFMA2, 128x128x8, conflict-free B columns)
// thread columns: [tx*4, tx*4+4) and [64+tx*4, 64+tx*4+4)
// ---------------------------------------------------------------------------
__global__ void __launch_bounds__(256, 2) gx_gemm_kernel(
        const float* __restrict__ A,
        const float* __restrict__ B) {
    __shared__ float As[2][8][128];
    __shared__ float Bs[2][8][128];

    const int tid = threadIdx.x;
    const int bm = blockIdx.y * 128;
    const int bn = blockIdx.x * 128;
    const int tx = tid & 15;
    const int ty = tid >> 4;

    u64 acc2[8][4];
#pragma unroll
    for (int i = 0; i < 8; i++)
#pragma unroll
        for (int j = 0; j < 4; j++) acc2[i][j] = 0ull;

    const int arow = tid >> 1;
    const int acol = (tid & 1) * 4;
    const int brow = tid >> 5;
    const int bcol = (tid & 31) * 4;
    const float* Ap = A + (size_t)(bm + arow) * HH + acol;
    const float* Bp = B + (size_t)brow * G3 + bn + bcol;

    float4 av = *(const float4*)Ap;
    float4 bv = *(const float4*)Bp;
    As[0][acol + 0][arow] = av.x;
    As[0][acol + 1][arow] = av.y;
    As[0][acol + 2][arow] = av.z;
    As[0][acol + 3][arow] = av.w;
    *(float4*)&Bs[0][brow][bcol] = bv;

    for (int it = 0; it < 128; it++) {
        __syncthreads();
        const int db = it & 1;
        if (it < 127) {
            Ap += 8;
            Bp += (size_t)8 * G3;
            av = *(const float4*)Ap;
            bv = *(const float4*)Bp;
        }
#pragma unroll
        for (int kk = 0; kk < 8; kk++) {
            float4 a0 = *(const float4*)&As[db][kk][ty * 8];
            float4 a1 = *(const float4*)&As[db][kk][ty * 8 + 4];
            ulonglong2 b01 = *(const ulonglong2*)&Bs[db][kk][tx * 4];
            ulonglong2 b23 = *(const ulonglong2*)&Bs[db][kk][64 + tx * 4];
            u64 ad[8];
            ad[0] = dup2(a0.x); ad[1] = dup2(a0.y);
            ad[2] = dup2(a0.z); ad[3] = dup2(a0.w);
            ad[4] = dup2(a1.x); ad[5] = dup2(a1.y);
            ad[6] = dup2(a1.z); ad[7] = dup2(a1.w);
#pragma unroll
            for (int i = 0; i < 8; i++) {
                fma2(acc2[i][0], ad[i], b01.x);
                fma2(acc2[i][1], ad[i], b01.y);
                fma2(acc2[i][2], ad[i], b23.x);
                fma2(acc2[i][3], ad[i], b23.y);
            }
        }
        if (it < 127) {
            const int nb = db ^ 1;
            As[nb][acol + 0][arow] = av.x;
            As[nb][acol + 1][arow] = av.y;
            As[nb][acol + 2][arow] = av.z;
            As[nb][acol + 3][arow] = av.w;
            *(float4*)&Bs[nb][brow][bcol] = bv;
        }
    }

#pragma unroll
    for (int i = 0; i < 8; i++) {
        float* Cp = g_gx + (size_t)(bm + ty * 8 + i) * G3 + bn;
        float2 c0 = unpk(acc2[i][0]);
        float2 c1 = unpk(acc2[i][1]);
        float2 c2 = unpk(acc2[i][2]);
        float2 c3 = unpk(acc2[i][3]);
        *(float4*)(Cp + tx * 4)      = make_float4(c0.x, c0.y, c1.x, c1.y);
        *(float4*)(Cp + 64 + tx * 4) = make_float4(c2.x, c2.y, c3.x, c3.y);
    }
}

// ---------------------------------------------------------------------------
__device__ __forceinline__ void grid_barrier(unsigned target) {
    __syncthreads();
    if (threadIdx.x == 0) {
        asm volatile("red.release.gpu.global.add.u32 [%0], 1;"
                     :: "l"(&g_bar) : "memory");
        unsigned v;
        do {
            asm volatile("ld.acquire.gpu.global.u32 %0, [%1];"
                         : "=r"(v) : "l"(&g_bar) : "memory");
        } while (v < target);
    }
    __syncthreads();
}

// ---------------------------------------------------------------------------
struct WaveCtx {
    const float* carry;
    const float* initial_h;
    const float* w_h;
    const float* bias;
    float* out;
    float* AsRaw;                 // union: As8[2][16][132] / As[2][32][64]
    float (*Bs)[32][128];
    const unsigned* rbs;
    const float** rowp;
    unsigned* posv;
};

__device__ __forceinline__ void set_rows(const WaveCtx& C, int phase,
                                         int mtile, int POSB,
                                         unsigned base, unsigned cnt) {
    const int tid = threadIdx.x;
    __syncthreads();
    if (tid < POSB) {
        int idx = mtile * POSB + tid;
        unsigned pos = 0xFFFFFFFFu;
        const float* rp = C.initial_h;
        if ((unsigned)idx < cnt) {
            pos = g_poslist[base + idx];
            int n = pos >> 10, t = (int)(pos & 1023);
            if (phase)
                rp = g_rh + (size_t)pos * HH;
            else if ((C.rbs[t] >> n) & 1u)
                rp = C.initial_h;
            else if (t == 0)
                rp = C.carry + (size_t)n * TT * HH;
            else
                rp = C.out + (size_t)(pos - 1) * HH;
        }
        C.posv[tid] = pos;
        C.rowp[tid] = rp;
    }
    __syncthreads();
}

// ---- epilogue for one 4-column segment ----
__device__ __forceinline__ void epi_seg(const WaveCtx& C, int phase,
                                        unsigned pos, int col0,
                                        const float* rowptr,
                                        u64 q0, u64 q1) {
    float2 f0 = unpk(q0), f1 = unpk(q1);
    float res[4] = {f0.x, f0.y, f1.x, f1.y};
    float4 gx0 = __ldcg((const float4*)(g_gx + (size_t)pos * G3 + col0));
    float gg[4] = {gx0.x, gx0.y, gx0.z, gx0.w};
    float4 bb0 = *(const float4*)(C.bias + col0);
    float bb[4] = {bb0.x, bb0.y, bb0.z, bb0.w};

    if (phase == 0 && col0 < HH) {                 // z-gate
        float o[4];
#pragma unroll
        for (int s = 0; s < 4; s++) o[s] = sigm(gg[s] + res[s] + bb[s]);
        *(float4*)(g_z + (size_t)pos * HH + col0) =
            make_float4(o[0], o[1], o[2], o[3]);
    } else if (phase == 0) {                       // r-gate -> rh
        const int j0 = col0 - HH;
        float4 h0 = __ldcg((const float4*)(rowptr + j0));
        float hh[4] = {h0.x, h0.y, h0.z, h0.w};
        float o[4];
#pragma unroll
        for (int s = 0; s < 4; s++)
            o[s] = sigm(gg[s] + res[s] + bb[s]) * hh[s];
        *(float4*)(g_rh + (size_t)pos * HH + j0) =
            make_float4(o[0], o[1], o[2], o[3]);
    } else {                                       // a-gate -> h_out
        const int j0 = col0 - 2 * HH;
        int n = pos >> 10, t = (int)(pos & 1023);
        const float* hp = ((C.rbs[t] >> n) & 1u) ? C.initial_h
                        : (t == 0 ? C.carry + (size_t)n * TT * HH
                                  : C.out + (size_t)(pos - 1) * HH);
        float4 h0 = __ldcg((const float4*)(hp + j0));
        float hh[4] = {h0.x, h0.y, h0.z, h0.w};
        float4 z0 = __ldcg((const float4*)(g_z + (size_t)pos * HH + j0));
        float zz[4] = {z0.x, z0.y, z0.z, z0.w};
        float o[4];
#pragma unroll
        for (int s = 0; s < 4; s++) {
            float a = tanhf(gg[s] + res[s] + bb[s]);
            o[s] = (1.f - zz[s]) * hh[s] + zz[s] * a;
        }
        float* op = C.out + (size_t)pos * HH + j0;
        float4 v = make_float4(o[0], o[1], o[2], o[3]);
        *(float4*)op               = v;
        *(float4*)(op + NTH_ELEMS) = v;
    }
}

__device__ __forceinline__ void epilogue_row(const WaveCtx& C, int phase,
                                             int colbase, int tx,
                                             unsigned pos,
                                             const float* rowptr,
                                             const u64* accq) {
    epi_seg(C, phase, pos, colbase + tx * 4,      rowptr, accq[0], accq[1]);
    epi_seg(C, phase, pos, colbase + 64 + tx * 4, rowptr, accq[2], accq[3]);
}

// ---------------------------------------------------------------------------
// big tile: 128 gathered rows x 128 cols, K=1024, kt=16, 8x8 per thread
// ---------------------------------------------------------------------------
#define AS8_STRIDE 132
__device__ void gemm_tile8(const WaveCtx& C, int phase, int mtile, int ntile,
                           unsigned base, unsigned cnt) {
    const int tid = threadIdx.x;
    const int tx = tid & 15;
    const int ty = tid >> 4;
    float* As8 = C.AsRaw;
    float (*Bs8)[16][128] = (float(*)[16][128])C.Bs;

    set_rows(C, phase, mtile, 128, base, cnt);

    const int colbase = (phase ? 2 * HH : 0) + ntile * 128;
    const float* wb = C.w_h + colbase;

    u64 acc[8][4];
#pragma unroll
    for (int r = 0; r < 8; r++)
#pragma unroll
        for (int j = 0; j < 4; j++) acc[r][j] = 0ull;

    float4 aL[2], bL[2];
    auto loadA = [&](int k0) {
#pragma unroll
        for (int p = 0; p < 2; p++) {
            int q = tid + 256 * p;
            int r = q >> 2, c4 = q & 3;
            aL[p] = __ldcg((const float4*)(C.rowp[r] + k0 + c4 * 4));
        }
    };
    auto storeA = [&](int buf) {
        float* bp = As8 + buf * 16 * AS8_STRIDE;
#pragma unroll
        for (int p = 0; p < 2; p++) {
            int q = tid + 256 * p;
            int r = q >> 2, c4 = q & 3;
            bp[(c4 * 4 + 0) * AS8_STRIDE + r] = aL[p].x;
            bp[(c4 * 4 + 1) * AS8_STRIDE + r] = aL[p].y;
            bp[(c4 * 4 + 2) * AS8_STRIDE + r] = aL[p].z;
            bp[(c4 * 4 + 3) * AS8_STRIDE + r] = aL[p].w;
        }
    };
    auto loadB = [&](int k0) {
#pragma unroll
        for (int p = 0; p < 2; p++) {
            int q = tid + 256 * p;
            int krow = q >> 5, col4 = q & 31;
            bL[p] = __ldcg((const float4*)(wb + (size_t)(k0 + krow) * G3 + col4 * 4));
        }
    };
    auto storeB = [&](int buf) {
#pragma unroll
        for (int p = 0; p < 2; p++) {
            int q = tid + 256 * p;
            int krow = q >> 5, col4 = q & 31;
            *(float4*)&Bs8[buf][krow][col4 * 4] = bL[p];
        }
    };

    loadA(0); loadB(0);
    storeA(0); storeB(0);
    for (int it = 0; it < 64; it++) {
        __syncthreads();
        const int db = it & 1;
        if (it < 63) { loadA((it + 1) * 16); loadB((it + 1) * 16); }
        const float* ab = As8 + db * 16 * AS8_STRIDE;
#pragma unroll
        for (int kk = 0; kk < 16; kk++) {
            float4 a0 = *(const float4*)(ab + kk * AS8_STRIDE + ty * 8);
            float4 a1 = *(const float4*)(ab + kk * AS8_STRIDE + ty * 8 + 4);
            ulonglong2 b01 = *(const ulonglong2*)&Bs8[db][kk][tx * 4];
            ulonglong2 b23 = *(const ulonglong2*)&Bs8[db][kk][64 + tx * 4];
            float av[8] = {a0.x, a0.y, a0.z, a0.w, a1.x, a1.y, a1.z, a1.w};
#pragma unroll
            for (int r = 0; r < 8; r++) {
                u64 ar = dup2(av[r]);
                fma2(acc[r][0], ar, b01.x);
                fma2(acc[r][1], ar, b01.y);
                fma2(acc[r][2], ar, b23.x);
                fma2(acc[r][3], ar, b23.y);
            }
        }
        if (it < 63) { const int nb = db ^ 1; storeA(nb); storeB(nb); }
    }

#pragma unroll
    for (int r = 0; r < 8; r++) {
        const int i = ty * 8 + r;
        unsigned pos = C.posv[i];
        if (pos == 0xFFFFFFFFu) continue;
        epilogue_row(C, phase, colbase, tx, pos, C.rowp[i], acc[r]);
    }
}

// ---------------------------------------------------------------------------
// medium/small tile: POSB (=R*16) rows x 128 cols, K=1024, kt=32
// ---------------------------------------------------------------------------
template<int R>
__device__ void gemm_tile(const WaveCtx& C, int phase, int mtile, int ntile,
                          unsigned base, unsigned cnt) {
    constexpr int POSB = R * 16;
    const int tid = threadIdx.x;
    const int tx = tid & 15;
    const int ty = tid >> 4;
    float (*As)[32][64] = (float(*)[32][64])C.AsRaw;

    set_rows(C, phase, mtile, POSB, base, cnt);

    const int colbase = (phase ? 2 * HH : 0) + ntile * 128;
    const float* wb = C.w_h + colbase;

    u64 acc[R][4];
#pragma unroll
    for (int r = 0; r < R; r++)
#pragma unroll
        for (int j = 0; j < 4; j++) acc[r][j] = 0ull;

    float4 aL[2], bL[4];
    auto loadA = [&](int k0) {
        if (R == 4) {
#pragma unroll
            for (int c = 0; c < 2; c++) {
                int q = tid + 256 * c;
                int i = q & 63, kc = q >> 6;
                aL[c] = __ldcg((const float4*)(C.rowp[i] + k0 + kc * 4));
            }
        } else {
            if (tid < 128) {
                int i = tid & 15, kc = tid >> 4;
                aL[0] = __ldcg((const float4*)(C.rowp[i] + k0 + kc * 4));
            }
        }
    };
    auto storeA = [&](int buf) {
        if (R == 4) {
#pragma unroll
            for (int c = 0; c < 2; c++) {
                int q = tid + 256 * c;
                int i = q & 63, kc = q >> 6;
                As[buf][kc * 4 + 0][i] = aL[c].x;
                As[buf][kc * 4 + 1][i] = aL[c].y;
                As[buf][kc * 4 + 2][i] = aL[c].z;
                As[buf][kc * 4 + 3][i] = aL[c].w;
            }
        } else {
            if (tid < 128) {
                int i = tid & 15, kc = tid >> 4;
                As[buf][kc * 4 + 0][i] = aL[0].x;
                As[buf][kc * 4 + 1][i] = aL[0].y;
                As[buf][kc * 4 + 2][i] = aL[0].z;
                As[buf][kc * 4 + 3][i] = aL[0].w;
            }
        }
    };
    auto loadB = [&](int k0) {
#pragma unroll
        for (int c = 0; c < 4; c++) {
            int q = tid + 256 * c;
            int row = q >> 5, c4 = q & 31;
            bL[c] = __ldcg((const float4*)(wb + (size_t)(k0 + row) * G3 + c4 * 4));
        }
    };
    auto storeB = [&](int buf) {
#pragma unroll
        for (int c = 0; c < 4; c++) {
            int q = tid + 256 * c;
            int row = q >> 5, c4 = q & 31;
            *(float4*)&C.Bs[buf][row][c4 * 4] = bL[c];
        }
    };

    loadA(0); loadB(0);
    storeA(0); storeB(0);
    for (int it = 0; it < 32; it++) {
        __syncthreads();
        const int db = it & 1;
        if (it < 31) { loadA((it + 1) * 32); loadB((it + 1) * 32); }
#pragma unroll
        for (int kk = 0; kk < 32; kk++) {
            float av[R];
            if (R == 4) {
                float4 a4 = *(const float4*)&As[db][kk][ty * 4];
                av[0] = a4.x; av[1] = a4.y; av[2] = a4.z; av[3] = a4.w;
            } else {
                av[0] = As[db][kk][ty];
            }
            ulonglong2 b01 = *(const ulonglong2*)&C.Bs[db][kk][tx * 4];
            ulonglong2 b23 = *(const ulonglong2*)&C.Bs[db][kk][64 + tx * 4];
#pragma unroll
            for (int r = 0; r < R; r++) {
                u64 ar = dup2(av[r]);
                fma2(acc[r][0], ar, b01.x);
                fma2(acc[r][1], ar, b01.y);
                fma2(acc[r][2], ar, b23.x);
                fma2(acc[r][3], ar, b23.y);
            }
        }
        if (it < 31) { const int nb = db ^ 1; storeA(nb); storeB(nb); }
    }

#pragma unroll
    for (int r = 0; r < R; r++) {
        const int i = ty * R + r;
        unsigned pos = C.posv[i];
        if (pos == 0xFFFFFFFFu) continue;
        epilogue_row(C, phase, colbase, tx, pos, C.rowp[i], acc[r]);
    }
}

// ---------------------------------------------------------------------------
__global__ void __launch_bounds__(WTHR, 2) wave_kernel(
        const float* __restrict__ carry,
        const float* __restrict__ initial_h,
        const float* __restrict__ w_h,
        const float* __restrict__ bias,
        float* __restrict__ out) {
    extern __shared__ char smw[];
    WaveCtx C;
    C.AsRaw = (float*)smw;                              // 16896 B
    C.Bs    = (float(*)[32][128])(smw + 16896);         // 32768 B
    unsigned* rbs = (unsigned*)(smw + 49664);           //  4096 B
    C.rowp  = (const float**)(smw + 53760);             //  1024 B
    C.posv  = (unsigned*)(smw + 54784);                 //   512 B
    C.rbs = rbs;
    C.carry = carry; C.initial_h = initial_h;
    C.w_h = w_h; C.bias = bias; C.out = out;

    const int tid = threadIdx.x;
    for (int t = tid; t < TT; t += WTHR) rbs[t] = g_rbits[t];
    __syncthreads();

    const unsigned nw = g_nwaves;
    unsigned bar_t = 0;

    for (unsigned wv = 0; wv < nw; wv++) {
        const unsigned base = g_waveoff[wv];
        const unsigned cnt  = g_waveoff[wv + 1] - base;
        const int kind = (cnt >= 1536) ? 2 : (cnt >= 256 ? 1 : 0);
        const int mt = (kind == 2) ? (int)((cnt + 127) >> 7)
                     : (kind == 1) ? (int)((cnt + 63) >> 6)
                                   : (int)((cnt + 15) >> 4);

        for (int tile = blockIdx.x; tile < mt * 16; tile += NCTA_W) {
            if (kind == 2)      gemm_tile8(C, 0, tile >> 4, tile & 15, base, cnt);
            else if (kind == 1) gemm_tile<4>(C, 0, tile >> 4, tile & 15, base, cnt);
            else                gemm_tile<1>(C, 0, tile >> 4, tile & 15, base, cnt);
        }
        bar_t += NCTA_W;
        grid_barrier(bar_t);

        for (int tile = blockIdx.x; tile < mt * 8; tile += NCTA_W) {
            if (kind == 2)      gemm_tile8(C, 1, tile >> 3, tile & 7, base, cnt);
            else if (kind == 1) gemm_tile<4>(C, 1, tile >> 3, tile & 7, base, cnt);
            else                gemm_tile<1>(C, 1, tile >> 3, tile & 7, base, cnt);
        }
        bar_t += NCTA_W;
        grid_barrier(bar_t);
    }
}

// ---------------------------------------------------------------------------
extern "C" void kernel_launch(void* const* d_in, const int* in_sizes, int n_in,
                              void* d_out, int out_size) {
    const float* x         = (const float*)d_in[0];
    const void*  reset     = d_in[1];
    const float* carry     = (const float*)d_in[2];
    const float* initial_h = (const float*)d_in[3];
    const float* w_i       = (const float*)d_in[4];
    const float* w_h       = (const float*)d_in[5];
    const float* b         = (const float*)d_in[6];
    float*       out       = (float*)d_out;
    (void)in_sizes; (void)n_in; (void)out_size;

    setup_kernel<<<1, 256>>>(reset, initial_h, out);

    dim3 ggrid(G3 / 128, (NB * TT) / 128);
    gx_gemm_kernel<<<ggrid, 256>>>(x, w_i);

    size_t smem = 55296;
    cudaFuncSetAttribute((const void*)wave_kernel,
                         cudaFuncAttributeMaxDynamicSharedMemorySize, (int)smem);
    wave_kernel<<<NCTA_W, WTHR, smem>>>(carry, initial_h, w_h, b, out);
}